// round 3
// baseline (speedup 1.0000x reference)
#include <cuda_runtime.h>
#include <math.h>

#define BN   8
#define HH   512
#define WW   1024
#define GG   104857
#define NTOT (BN * GG)          // 838856  (divisible by 4)
#define NQUAD (NTOT / 4)        // 209714
#define HBINS 65536

// ---------------- device scratch (no allocations allowed) ----------------
__device__ float        g_loss[NTOT];
__device__ unsigned int g_hcnt16[HBINS];   // top-16-bit count histogram
__device__ unsigned int g_hcnt_lo[HBINS];  // low-16-bit count histogram (bin-j only)
__device__ float        g_hsum_lo[HBINS];  // low-16-bit sum histogram  (bin-j only)
__device__ double       g_sum_valid;
__device__ double       g_sum_below;       // sum of values with top16 < g_bin
__device__ unsigned int g_n;
__device__ unsigned int g_bin;
__device__ unsigned int g_krem;

// ---------------- init: clear all three histograms + scalars ----------------
__global__ void init_kernel() {
    unsigned int i = blockIdx.x * blockDim.x + threadIdx.x;  // 768*256 = 196608
    if (i < HBINS) {
        g_hcnt16[i] = 0u;
    } else if (i < 2 * HBINS) {
        g_hcnt_lo[i - HBINS] = 0u;
    } else {
        g_hsum_lo[i - 2 * HBINS] = 0.0f;
    }
    if (i == 0) { g_sum_valid = 0.0; g_sum_below = 0.0; }
}

// ---------------- main compute: loss per group + top-16 count hist ----------------
__global__ void __launch_bounds__(256)
compute_kernel(const float* __restrict__ pred,
               const float* __restrict__ tgt,
               const float* __restrict__ intr,
               const int*   __restrict__ p1,
               const int*   __restrict__ p2,
               const int*   __restrict__ p3)
{
    const float EPS   = 1e-6f;
    const float DCOS  = 0.867f;
    const float DDIFF = 0.005f;
    const float DZ    = 1e-5f;
    const float INF_F = __int_as_float(0x7f800000);

    int i = blockIdx.x * blockDim.x + threadIdx.x;
    if (i >= NTOT) return;

    int b = i / GG;
    const float* tb = tgt  + b * (HH * WW);
    const float* pb = pred + b * (HH * WW);
    float f    = __ldg(intr + b * 9 + 0);
    float u0   = __ldg(intr + b * 9 + 2);
    float v0   = __ldg(intr + b * 9 + 5);
    float invf = 1.0f / f;

    int id0 = __ldg(p1 + i);
    int id1 = __ldg(p2 + i);
    int id2 = __ldg(p3 + i);

    // issue all gathers up front for MLP
    float dt0 = __ldg(tb + id0), dt1 = __ldg(tb + id1), dt2 = __ldg(tb + id2);
    float dp0 = __ldg(pb + id0), dp1 = __ldg(pb + id1), dp2 = __ldg(pb + id2);

    float Px[3], Py[3], Pz[3], Qx[3], Qy[3], Qz[3];
    {
        int ids[3] = {id0, id1, id2};
        float dts[3] = {dt0, dt1, dt2};
        float dps[3] = {dp0, dp1, dp2};
        #pragma unroll
        for (int j = 0; j < 3; j++) {
            int id  = ids[j];
            float u = (float)(id & (WW - 1)) - u0;
            float v = (float)(id >> 10)      - v0;
            float dt = dts[j], dp = dps[j];
            Px[j] = u * dt * invf;  Py[j] = v * dt * invf;  Pz[j] = dt;
            Qx[j] = u * dp * invf;  Qy[j] = v * dp * invf;  Qz[j] = dp;
        }
    }

    // GT diffs: D0 = p2-p1, D1 = p3-p1, D2 = p3-p2
    float Dx[3], Dy[3], Dz[3];
    Dx[0] = Px[1] - Px[0]; Dy[0] = Py[1] - Py[0]; Dz[0] = Pz[1] - Pz[0];
    Dx[1] = Px[2] - Px[0]; Dy[1] = Py[2] - Py[0]; Dz[1] = Pz[2] - Pz[0];
    Dx[2] = Px[2] - Px[1]; Dy[2] = Py[2] - Py[1]; Dz[2] = Pz[2] - Pz[1];

    // Gram matrix of diffs (symmetric)
    float e00 = Dx[0]*Dx[0] + Dy[0]*Dy[0] + Dz[0]*Dz[0];
    float e11 = Dx[1]*Dx[1] + Dy[1]*Dy[1] + Dz[1]*Dz[1];
    float e22 = Dx[2]*Dx[2] + Dy[2]*Dy[2] + Dz[2]*Dz[2];
    float e01 = Dx[0]*Dx[1] + Dy[0]*Dy[1] + Dz[0]*Dz[1];
    float e02 = Dx[0]*Dx[2] + Dy[0]*Dy[2] + Dz[0]*Dz[2];
    float e12 = Dx[1]*Dx[2] + Dy[1]*Dy[2] + Dz[1]*Dz[2];

    float qn0 = sqrtf(e00), qn1 = sqrtf(e11), qn2 = sqrtf(e22);

    // |e/(qn_i*qn_j + EPS)| > DCOS  <=>  |e| > DCOS*(qn_i*qn_j + EPS)
    int cnt = 0;
    cnt += (fabsf(e00) > DCOS * (qn0 * qn0 + EPS)) ? 1 : 0;
    cnt += (fabsf(e11) > DCOS * (qn1 * qn1 + EPS)) ? 1 : 0;
    cnt += (fabsf(e22) > DCOS * (qn2 * qn2 + EPS)) ? 1 : 0;
    cnt += (fabsf(e01) > DCOS * (qn0 * qn1 + EPS)) ? 2 : 0;
    cnt += (fabsf(e02) > DCOS * (qn0 * qn2 + EPS)) ? 2 : 0;
    cnt += (fabsf(e12) > DCOS * (qn1 * qn2 + EPS)) ? 2 : 0;
    bool mask_cos = cnt > 3;

    bool mask_pad = (Pz[0] > DZ) && (Pz[1] > DZ) && (Pz[2] > DZ);
    bool mx = (fabsf(Dx[0]) < DDIFF) || (fabsf(Dx[1]) < DDIFF) || (fabsf(Dx[2]) < DDIFF);
    bool my = (fabsf(Dy[0]) < DDIFF) || (fabsf(Dy[1]) < DDIFF) || (fabsf(Dy[2]) < DDIFF);
    bool mz = (fabsf(Dz[0]) < DDIFF) || (fabsf(Dz[1]) < DDIFF) || (fabsf(Dz[2]) < DDIFF);
    bool valid = mask_pad && !((mx && my && mz) || mask_cos);

    // faithful replication of pred_g[pred_g[:,:,2,:]==0] = 1e-4 broadcast quirk:
    // z of point j == 0  =>  coord j of ALL points := 1e-4
    bool c0 = (Qz[0] == 0.0f), c1 = (Qz[1] == 0.0f), c2 = (Qz[2] == 0.0f);
    if (c0) { Qx[0] = 1e-4f; Qx[1] = 1e-4f; Qx[2] = 1e-4f; }
    if (c1) { Qy[0] = 1e-4f; Qy[1] = 1e-4f; Qy[2] = 1e-4f; }
    if (c2) { Qz[0] = 1e-4f; Qz[1] = 1e-4f; Qz[2] = 1e-4f; }

    // GT normal: cross(D0, D1)
    float ngx = Dy[0] * Dz[1] - Dz[0] * Dy[1];
    float ngy = Dz[0] * Dx[1] - Dx[0] * Dz[1];
    float ngz = Dx[0] * Dy[1] - Dy[0] * Dx[1];
    float nng = sqrtf(ngx * ngx + ngy * ngy + ngz * ngz);
    if (nng == 0.0f) nng = EPS;
    float ig = 1.0f / nng;
    ngx *= ig; ngy *= ig; ngz *= ig;

    // pred normal
    float ax = Qx[1] - Qx[0], ay = Qy[1] - Qy[0], az = Qz[1] - Qz[0];
    float bx = Qx[2] - Qx[0], by = Qy[2] - Qy[0], bz = Qz[2] - Qz[0];
    float npx = ay * bz - az * by;
    float npy = az * bx - ax * bz;
    float npz = ax * by - ay * bx;
    float nnp = sqrtf(npx * npx + npy * npy + npz * npz);
    if (nnp == 0.0f) nnp = EPS;
    float ip = 1.0f / nnp;
    npx *= ip; npy *= ip; npz *= ip;

    float loss = fabsf(ngx - npx) + fabsf(ngy - npy) + fabsf(ngz - npz);

    float out = valid ? loss : INF_F;   // +inf sinks past all finite values
    g_loss[i] = out;
    atomicAdd(&g_hcnt16[__float_as_uint(out) >> 16], 1u);  // RED, no return
}

// ---------------- resolve top-16: find bin holding the k-th smallest ----------------
__global__ void resolve16_kernel()
{
    __shared__ unsigned int ccnt[256];
    int t = threadIdx.x;
    unsigned int c = 0;
    int base = t << 8;
    #pragma unroll 8
    for (int j = 0; j < 256; j++) c += g_hcnt16[base + j];
    ccnt[t] = c;
    __syncthreads();

    if (t == 0) {
        unsigned int n = NTOT - g_hcnt16[0x7f80];  // finite (= valid) count
        unsigned int k = n >> 2;                   // drop n//4 smallest
        g_n = n;

        unsigned int cum = 0; int chunk = 0;
        for (int ch = 0; ch < 256; ch++) {
            if (cum + ccnt[ch] >= k) { chunk = ch; break; }
            cum += ccnt[ch];
        }
        unsigned int bin = (unsigned int)(chunk << 8), krem = 0;
        for (int j = chunk << 8; ; j++) {
            unsigned int cj = g_hcnt16[j];
            if (cum + cj >= k) { bin = (unsigned int)j; krem = k - cum; break; }
            cum += cj;
        }
        g_bin  = bin;
        g_krem = krem;
    }
}

// ---------------- passB: Σ_valid, Σ(top16<bin), low-16 hist of bin-j values ----------------
__global__ void __launch_bounds__(256)
passB_kernel()
{
    __shared__ float sh_v[8], sh_b[8];

    unsigned int j = g_bin;
    float sv = 0.0f, sb = 0.0f;

    int q = blockIdx.x * blockDim.x + threadIdx.x;
    if (q < NQUAD) {
        float4 v4 = reinterpret_cast<const float4*>(g_loss)[q];
        float vs[4] = {v4.x, v4.y, v4.z, v4.w};
        #pragma unroll
        for (int e = 0; e < 4; e++) {
            float v = vs[e];
            unsigned int bits = __float_as_uint(v);
            if (bits < 0x7f800000u) sv += v;       // finite = valid
            unsigned int top = bits >> 16;
            if (top < j) {
                sb += v;
            } else if (top == j) {
                atomicAdd(&g_hcnt_lo[bits & 0xffffu], 1u);
                atomicAdd(&g_hsum_lo[bits & 0xffffu], v);
            }
        }
    }

    #pragma unroll
    for (int o = 16; o > 0; o >>= 1) {
        sv += __shfl_down_sync(0xffffffffu, sv, o);
        sb += __shfl_down_sync(0xffffffffu, sb, o);
    }
    int wid = threadIdx.x >> 5, lid = threadIdx.x & 31;
    if (lid == 0) { sh_v[wid] = sv; sh_b[wid] = sb; }
    __syncthreads();
    if (threadIdx.x == 0) {
        float tv = 0.0f, tb = 0.0f;
        #pragma unroll
        for (int w = 0; w < 8; w++) { tv += sh_v[w]; tb += sh_b[w]; }
        atomicAdd(&g_sum_valid, (double)tv);
        atomicAdd(&g_sum_below, (double)tb);
    }
}

// ---------------- resolve low-16 + assemble final scalar ----------------
__global__ void finish_kernel(float* __restrict__ out)
{
    __shared__ unsigned int ccnt[256];
    int t = threadIdx.x;
    unsigned int c = 0;
    int base = t << 8;
    #pragma unroll 8
    for (int j = 0; j < 256; j++) c += g_hcnt_lo[base + j];
    ccnt[t] = c;
    __syncthreads();

    if (t == 0) {
        unsigned int krem = g_krem;

        unsigned int cum = 0; int chunk = 0;
        for (int ch = 0; ch < 256; ch++) {
            if (cum + ccnt[ch] >= krem) { chunk = ch; break; }
            cum += ccnt[ch];
        }
        // rescan fine bins of the chunk, accumulating exact sum below
        double sum_lo_below = 0.0;
        // sum of hsum_lo over full chunks below `chunk`
        for (int ch = 0; ch < chunk; ch++) {
            // ccnt only has counts; need sums: walk those chunks' sums
            // (256*chunk loads worst case 64K — but chunk is found early in
            //  practice; bound is acceptable for a 1-block epilogue)
            ;
        }
        // accumulate sums for all bins below the selected fine bin
        unsigned int cum2 = 0; unsigned int lobin = (unsigned int)(chunk << 8);
        // first add sums of all full chunks below
        double sum_full = 0.0;
        for (int ch = 0; ch < chunk; ch++) {
            int b0 = ch << 8;
            float s = 0.0f;
            for (int j = 0; j < 256; j++) s += g_hsum_lo[b0 + j];
            sum_full += (double)s;
        }
        cum2 = cum;  // counts below chunk already accumulated
        for (int j = chunk << 8; ; j++) {
            unsigned int cj = g_hcnt_lo[j];
            if (cum2 + cj >= krem) { lobin = (unsigned int)j; break; }
            cum2 += cj;
            sum_lo_below += (double)g_hsum_lo[j];
        }
        float tf = __uint_as_float((g_bin << 16) | lobin);
        double sum_small = g_sum_below + sum_full + sum_lo_below
                         + (double)(krem - cum2) * (double)tf;
        unsigned int n = g_n;
        long long d = (long long)n - (long long)(n >> 2);
        if (d < 1) d = 1;
        out[0] = (float)((g_sum_valid - sum_small) / (double)d);
    }
}

// ---------------- launch ----------------
extern "C" void kernel_launch(void* const* d_in, const int* in_sizes, int n_in,
                              void* d_out, int out_size)
{
    const float* pred = (const float*)d_in[0];
    const float* tgt  = (const float*)d_in[1];
    // d_in[2] = mask (already baked into p1/p2/p3; unused)
    const float* intr = (const float*)d_in[3];
    const int*   p1   = (const int*)d_in[4];
    const int*   p2   = (const int*)d_in[5];
    const int*   p3   = (const int*)d_in[6];
    float* out = (float*)d_out;

    init_kernel<<<768, 256>>>();                       // 196608 = 3*65536 words
    compute_kernel<<<(NTOT + 255) / 256, 256>>>(pred, tgt, intr, p1, p2, p3);
    resolve16_kernel<<<1, 256>>>();
    passB_kernel<<<(NQUAD + 255) / 256, 256>>>();
    finish_kernel<<<1, 256>>>(out);
}

// round 4
// speedup vs baseline: 2.8468x; 2.8468x over previous
#include <cuda_runtime.h>
#include <math.h>

#define BN   8
#define HH   512
#define WW   1024
#define GG   104857
#define NTOT (BN * GG)          // 838856  (divisible by 4)
#define NQUAD (NTOT / 4)        // 209714
#define HBINS 65536

// ---------------- device scratch (no allocations allowed) ----------------
__device__ __align__(16) float        g_loss[NTOT];
__device__ __align__(16) unsigned int g_hcnt16[HBINS];   // top-16-bit count histogram
__device__ __align__(16) unsigned int g_hcnt_lo[HBINS];  // low-16-bit count histogram (bin-b only)
__device__ __align__(16) float        g_hsum_lo[HBINS];  // low-16-bit sum histogram  (bin-b only)
__device__ double       g_sum_valid;
__device__ double       g_sum_below;       // sum of values with top16 < g_bin
__device__ unsigned int g_n;
__device__ unsigned int g_bin;
__device__ unsigned int g_krem;

// ---------------- init: clear all three histograms + scalars ----------------
__global__ void init_kernel() {
    unsigned int i = blockIdx.x * blockDim.x + threadIdx.x;  // 768*256 = 196608
    if (i < HBINS) {
        g_hcnt16[i] = 0u;
    } else if (i < 2 * HBINS) {
        g_hcnt_lo[i - HBINS] = 0u;
    } else {
        g_hsum_lo[i - 2 * HBINS] = 0.0f;
    }
    if (i == 0) { g_sum_valid = 0.0; g_sum_below = 0.0; }
}

// ---------------- main compute: loss per group + top-16 count hist ----------------
__global__ void __launch_bounds__(256)
compute_kernel(const float* __restrict__ pred,
               const float* __restrict__ tgt,
               const float* __restrict__ intr,
               const int*   __restrict__ p1,
               const int*   __restrict__ p2,
               const int*   __restrict__ p3)
{
    const float EPS   = 1e-6f;
    const float DCOS  = 0.867f;
    const float DDIFF = 0.005f;
    const float DZ    = 1e-5f;
    const float INF_F = __int_as_float(0x7f800000);

    int i = blockIdx.x * blockDim.x + threadIdx.x;
    if (i >= NTOT) return;

    int b = i / GG;
    const float* tb = tgt  + b * (HH * WW);
    const float* pb = pred + b * (HH * WW);
    float f    = __ldg(intr + b * 9 + 0);
    float u0   = __ldg(intr + b * 9 + 2);
    float v0   = __ldg(intr + b * 9 + 5);
    float invf = 1.0f / f;

    int id0 = __ldg(p1 + i);
    int id1 = __ldg(p2 + i);
    int id2 = __ldg(p3 + i);

    // issue all gathers up front for MLP
    float dt0 = __ldg(tb + id0), dt1 = __ldg(tb + id1), dt2 = __ldg(tb + id2);
    float dp0 = __ldg(pb + id0), dp1 = __ldg(pb + id1), dp2 = __ldg(pb + id2);

    float Px[3], Py[3], Pz[3], Qx[3], Qy[3], Qz[3];
    {
        int ids[3] = {id0, id1, id2};
        float dts[3] = {dt0, dt1, dt2};
        float dps[3] = {dp0, dp1, dp2};
        #pragma unroll
        for (int j = 0; j < 3; j++) {
            int id  = ids[j];
            float u = (float)(id & (WW - 1)) - u0;
            float v = (float)(id >> 10)      - v0;
            float dt = dts[j], dp = dps[j];
            Px[j] = u * dt * invf;  Py[j] = v * dt * invf;  Pz[j] = dt;
            Qx[j] = u * dp * invf;  Qy[j] = v * dp * invf;  Qz[j] = dp;
        }
    }

    // GT diffs: D0 = p2-p1, D1 = p3-p1, D2 = p3-p2
    float Dx[3], Dy[3], Dz[3];
    Dx[0] = Px[1] - Px[0]; Dy[0] = Py[1] - Py[0]; Dz[0] = Pz[1] - Pz[0];
    Dx[1] = Px[2] - Px[0]; Dy[1] = Py[2] - Py[0]; Dz[1] = Pz[2] - Pz[0];
    Dx[2] = Px[2] - Px[1]; Dy[2] = Py[2] - Py[1]; Dz[2] = Pz[2] - Pz[1];

    // Gram matrix of diffs (symmetric)
    float e00 = Dx[0]*Dx[0] + Dy[0]*Dy[0] + Dz[0]*Dz[0];
    float e11 = Dx[1]*Dx[1] + Dy[1]*Dy[1] + Dz[1]*Dz[1];
    float e22 = Dx[2]*Dx[2] + Dy[2]*Dy[2] + Dz[2]*Dz[2];
    float e01 = Dx[0]*Dx[1] + Dy[0]*Dy[1] + Dz[0]*Dz[1];
    float e02 = Dx[0]*Dx[2] + Dy[0]*Dy[2] + Dz[0]*Dz[2];
    float e12 = Dx[1]*Dx[2] + Dy[1]*Dy[2] + Dz[1]*Dz[2];

    float qn0 = sqrtf(e00), qn1 = sqrtf(e11), qn2 = sqrtf(e22);

    // |e/(qn_i*qn_j + EPS)| > DCOS  <=>  |e| > DCOS*(qn_i*qn_j + EPS)
    int cnt = 0;
    cnt += (fabsf(e00) > DCOS * (qn0 * qn0 + EPS)) ? 1 : 0;
    cnt += (fabsf(e11) > DCOS * (qn1 * qn1 + EPS)) ? 1 : 0;
    cnt += (fabsf(e22) > DCOS * (qn2 * qn2 + EPS)) ? 1 : 0;
    cnt += (fabsf(e01) > DCOS * (qn0 * qn1 + EPS)) ? 2 : 0;
    cnt += (fabsf(e02) > DCOS * (qn0 * qn2 + EPS)) ? 2 : 0;
    cnt += (fabsf(e12) > DCOS * (qn1 * qn2 + EPS)) ? 2 : 0;
    bool mask_cos = cnt > 3;

    bool mask_pad = (Pz[0] > DZ) && (Pz[1] > DZ) && (Pz[2] > DZ);
    bool mx = (fabsf(Dx[0]) < DDIFF) || (fabsf(Dx[1]) < DDIFF) || (fabsf(Dx[2]) < DDIFF);
    bool my = (fabsf(Dy[0]) < DDIFF) || (fabsf(Dy[1]) < DDIFF) || (fabsf(Dy[2]) < DDIFF);
    bool mz = (fabsf(Dz[0]) < DDIFF) || (fabsf(Dz[1]) < DDIFF) || (fabsf(Dz[2]) < DDIFF);
    bool valid = mask_pad && !((mx && my && mz) || mask_cos);

    // faithful replication of pred_g[pred_g[:,:,2,:]==0] = 1e-4 broadcast quirk:
    // z of point j == 0  =>  coord j of ALL points := 1e-4
    bool c0 = (Qz[0] == 0.0f), c1 = (Qz[1] == 0.0f), c2 = (Qz[2] == 0.0f);
    if (c0) { Qx[0] = 1e-4f; Qx[1] = 1e-4f; Qx[2] = 1e-4f; }
    if (c1) { Qy[0] = 1e-4f; Qy[1] = 1e-4f; Qy[2] = 1e-4f; }
    if (c2) { Qz[0] = 1e-4f; Qz[1] = 1e-4f; Qz[2] = 1e-4f; }

    // GT normal: cross(D0, D1)
    float ngx = Dy[0] * Dz[1] - Dz[0] * Dy[1];
    float ngy = Dz[0] * Dx[1] - Dx[0] * Dz[1];
    float ngz = Dx[0] * Dy[1] - Dy[0] * Dx[1];
    float nng = sqrtf(ngx * ngx + ngy * ngy + ngz * ngz);
    if (nng == 0.0f) nng = EPS;
    float ig = 1.0f / nng;
    ngx *= ig; ngy *= ig; ngz *= ig;

    // pred normal
    float ax = Qx[1] - Qx[0], ay = Qy[1] - Qy[0], az = Qz[1] - Qz[0];
    float bx = Qx[2] - Qx[0], by = Qy[2] - Qy[0], bz = Qz[2] - Qz[0];
    float npx = ay * bz - az * by;
    float npy = az * bx - ax * bz;
    float npz = ax * by - ay * bx;
    float nnp = sqrtf(npx * npx + npy * npy + npz * npz);
    if (nnp == 0.0f) nnp = EPS;
    float ip = 1.0f / nnp;
    npx *= ip; npy *= ip; npz *= ip;

    float loss = fabsf(ngx - npx) + fabsf(ngy - npy) + fabsf(ngz - npz);

    float out = valid ? loss : INF_F;   // +inf sinks past all finite values
    g_loss[i] = out;
    atomicAdd(&g_hcnt16[__float_as_uint(out) >> 16], 1u);  // RED, no return
}

// ---------------- resolve top-16 (cooperative; no serial global scans) ----------------
__global__ void resolve16_kernel()
{
    __shared__ unsigned int s_ccnt[256];
    __shared__ int          s_chunk;
    __shared__ unsigned int s_cum;
    __shared__ unsigned int s_fcnt[256];

    int t = threadIdx.x;

    // each thread reduces its 256-bin chunk with uint4 loads
    const uint4* h4 = reinterpret_cast<const uint4*>(g_hcnt16);
    unsigned int c = 0;
    int base4 = t << 6;                    // 64 uint4 per chunk
    #pragma unroll 8
    for (int j = 0; j < 64; j++) {
        uint4 v = h4[base4 + j];
        c += v.x + v.y + v.z + v.w;
    }
    s_ccnt[t] = c;
    __syncthreads();

    if (t == 0) {
        unsigned int n = NTOT - g_hcnt16[0x7f80];  // finite (= valid) count
        unsigned int k = n >> 2;                   // drop n//4 smallest
        g_n = n;

        unsigned int cum = 0; int chunk = 255;
        #pragma unroll 4
        for (int ch = 0; ch < 256; ch++) {
            unsigned int cc = s_ccnt[ch];
            if (cum + cc >= k) { chunk = ch; break; }
            cum += cc;
        }
        s_chunk = chunk;
        s_cum   = cum;
        g_krem  = k;      // stash k temporarily (fixed below)
    }
    __syncthreads();

    // cooperatively load the selected chunk's fine bins into shared
    int chunk = s_chunk;
    s_fcnt[t] = g_hcnt16[(chunk << 8) + t];
    __syncthreads();

    if (t == 0) {
        unsigned int k   = g_krem;
        unsigned int cum = s_cum;
        unsigned int bin = (unsigned int)(chunk << 8), krem = 0;
        #pragma unroll 4
        for (int j = 0; j < 256; j++) {
            unsigned int cj = s_fcnt[j];
            if (cum + cj >= k) { bin = (unsigned int)((chunk << 8) + j); krem = k - cum; break; }
            cum += cj;
        }
        g_bin  = bin;
        g_krem = krem;
    }
}

// ---------------- passB: Σ_valid, Σ(top16<bin), low-16 hist of bin-b values ----------------
__global__ void __launch_bounds__(256)
passB_kernel()
{
    __shared__ float sh_v[8], sh_b[8];

    unsigned int bsel = g_bin;
    float sv = 0.0f, sb = 0.0f;

    int q = blockIdx.x * blockDim.x + threadIdx.x;
    if (q < NQUAD) {
        float4 v4 = reinterpret_cast<const float4*>(g_loss)[q];
        float vs[4] = {v4.x, v4.y, v4.z, v4.w};
        #pragma unroll
        for (int e = 0; e < 4; e++) {
            float v = vs[e];
            unsigned int bits = __float_as_uint(v);
            if (bits < 0x7f800000u) sv += v;       // finite = valid
            unsigned int top = bits >> 16;
            if (top < bsel) {
                sb += v;
            } else if (top == bsel) {
                atomicAdd(&g_hcnt_lo[bits & 0xffffu], 1u);
                atomicAdd(&g_hsum_lo[bits & 0xffffu], v);
            }
        }
    }

    #pragma unroll
    for (int o = 16; o > 0; o >>= 1) {
        sv += __shfl_down_sync(0xffffffffu, sv, o);
        sb += __shfl_down_sync(0xffffffffu, sb, o);
    }
    int wid = threadIdx.x >> 5, lid = threadIdx.x & 31;
    if (lid == 0) { sh_v[wid] = sv; sh_b[wid] = sb; }
    __syncthreads();
    if (threadIdx.x == 0) {
        float tv = 0.0f, tb = 0.0f;
        #pragma unroll
        for (int w = 0; w < 8; w++) { tv += sh_v[w]; tb += sh_b[w]; }
        atomicAdd(&g_sum_valid, (double)tv);
        atomicAdd(&g_sum_below, (double)tb);
    }
}

// ---------------- resolve low-16 (cooperative) + assemble final scalar ----------------
__global__ void finish_kernel(float* __restrict__ out)
{
    __shared__ unsigned int s_ccnt[256];
    __shared__ float        s_csum[256];
    __shared__ int          s_chunk;
    __shared__ unsigned int s_cum;
    __shared__ double       s_sumfull;
    __shared__ unsigned int s_fcnt[256];
    __shared__ float        s_fsum[256];

    int t = threadIdx.x;

    // per-thread chunk reduction of count AND sum with vector loads
    const uint4*   c4 = reinterpret_cast<const uint4*>(g_hcnt_lo);
    const float4*  f4 = reinterpret_cast<const float4*>(g_hsum_lo);
    unsigned int c = 0;
    float        s = 0.0f;
    int base4 = t << 6;
    #pragma unroll 8
    for (int j = 0; j < 64; j++) {
        uint4  cv = c4[base4 + j];
        float4 sv = f4[base4 + j];
        c += cv.x + cv.y + cv.z + cv.w;
        s += sv.x + sv.y + sv.z + sv.w;
    }
    s_ccnt[t] = c;
    s_csum[t] = s;
    __syncthreads();

    if (t == 0) {
        unsigned int krem = g_krem;
        unsigned int cum = 0; int chunk = 255;
        double sumfull = 0.0;
        for (int ch = 0; ch < 256; ch++) {
            unsigned int cc = s_ccnt[ch];
            if (cum + cc >= krem) { chunk = ch; break; }
            cum += cc;
            sumfull += (double)s_csum[ch];
        }
        s_chunk   = chunk;
        s_cum     = cum;
        s_sumfull = sumfull;
    }
    __syncthreads();

    // cooperatively load the selected chunk's fine bins
    int chunk = s_chunk;
    s_fcnt[t] = g_hcnt_lo[(chunk << 8) + t];
    s_fsum[t] = g_hsum_lo[(chunk << 8) + t];
    __syncthreads();

    if (t == 0) {
        unsigned int krem = g_krem;
        unsigned int cum2 = s_cum;
        double sum_lo_below = s_sumfull;
        unsigned int lobin = (unsigned int)(chunk << 8);
        for (int j = 0; j < 256; j++) {
            unsigned int cj = s_fcnt[j];
            if (cum2 + cj >= krem) { lobin = (unsigned int)((chunk << 8) + j); break; }
            cum2 += cj;
            sum_lo_below += (double)s_fsum[j];
        }
        float tf = __uint_as_float((g_bin << 16) | (lobin & 0xffffu));
        double sum_small = g_sum_below + sum_lo_below
                         + (double)(krem - cum2) * (double)tf;
        unsigned int n = g_n;
        long long d = (long long)n - (long long)(n >> 2);
        if (d < 1) d = 1;
        out[0] = (float)((g_sum_valid - sum_small) / (double)d);
    }
}

// ---------------- launch ----------------
extern "C" void kernel_launch(void* const* d_in, const int* in_sizes, int n_in,
                              void* d_out, int out_size)
{
    const float* pred = (const float*)d_in[0];
    const float* tgt  = (const float*)d_in[1];
    // d_in[2] = mask (already baked into p1/p2/p3; unused)
    const float* intr = (const float*)d_in[3];
    const int*   p1   = (const int*)d_in[4];
    const int*   p2   = (const int*)d_in[5];
    const int*   p3   = (const int*)d_in[6];
    float* out = (float*)d_out;

    init_kernel<<<768, 256>>>();                       // 196608 = 3*65536 words
    compute_kernel<<<(NTOT + 255) / 256, 256>>>(pred, tgt, intr, p1, p2, p3);
    resolve16_kernel<<<1, 256>>>();
    passB_kernel<<<(NQUAD + 255) / 256, 256>>>();
    finish_kernel<<<1, 256>>>(out);
}

// round 5
// speedup vs baseline: 15.8437x; 5.5653x over previous
#include <cuda_runtime.h>
#include <math.h>

#define BN   8
#define HH   512
#define WW   1024
#define GG   104857
#define NTOT (BN * GG)          // 838856  (divisible by 4)
#define NQUAD (NTOT / 4)        // 209714
#define HBINS 65536

// ---------------- device scratch (no allocations allowed) ----------------
__device__ __align__(16) float        g_loss[NTOT];
__device__ __align__(16) unsigned int g_hist8[256];     // top-8-bit count histogram
__device__ __align__(16) unsigned int g_hist8b[256];    // byte-2 hist (top8==b8 only)
__device__ __align__(16) unsigned int g_hcnt_lo[HBINS]; // low-16-bit counts (top16==g_bin)
__device__ __align__(16) float        g_hsum_lo[HBINS]; // low-16-bit sums   (top16==g_bin)
__device__ double       g_sum_valid;
__device__ double       g_sum_below;       // sum of values with top16 < g_bin
__device__ unsigned int g_n;
__device__ unsigned int g_b8;
__device__ unsigned int g_k1;
__device__ unsigned int g_bin;
__device__ unsigned int g_krem;

// ---------------- init: clear histograms + scalars ----------------
__global__ void init_kernel() {
    unsigned int i = blockIdx.x * blockDim.x + threadIdx.x;  // 516*256 = 132096
    if (i < HBINS) {
        g_hcnt_lo[i] = 0u;
    } else if (i < 2 * HBINS) {
        g_hsum_lo[i - HBINS] = 0.0f;
    } else if (i < 2 * HBINS + 256) {
        g_hist8[i - 2 * HBINS] = 0u;
    } else if (i < 2 * HBINS + 512) {
        g_hist8b[i - 2 * HBINS - 256] = 0u;
    }
    if (i == 0) { g_sum_valid = 0.0; g_sum_below = 0.0; }
}

// ---------------- main compute: loss per group + top-8 shared hist ----------------
__global__ void __launch_bounds__(256)
compute_kernel(const float* __restrict__ pred,
               const float* __restrict__ tgt,
               const float* __restrict__ intr,
               const int*   __restrict__ p1,
               const int*   __restrict__ p2,
               const int*   __restrict__ p3)
{
    __shared__ unsigned int sh[256];
    sh[threadIdx.x] = 0u;
    __syncthreads();

    const float EPS   = 1e-6f;
    const float DCOS  = 0.867f;
    const float DDIFF = 0.005f;
    const float DZ    = 1e-5f;
    const float INF_F = __int_as_float(0x7f800000);

    for (int i = blockIdx.x * blockDim.x + threadIdx.x; i < NTOT;
         i += gridDim.x * blockDim.x)
    {
        int b = i / GG;
        const float* tb = tgt  + b * (HH * WW);
        const float* pb = pred + b * (HH * WW);
        float f    = __ldg(intr + b * 9 + 0);
        float u0   = __ldg(intr + b * 9 + 2);
        float v0   = __ldg(intr + b * 9 + 5);
        float invf = 1.0f / f;

        int id0 = __ldg(p1 + i);
        int id1 = __ldg(p2 + i);
        int id2 = __ldg(p3 + i);

        // issue all gathers up front for MLP
        float dt0 = __ldg(tb + id0), dt1 = __ldg(tb + id1), dt2 = __ldg(tb + id2);
        float dp0 = __ldg(pb + id0), dp1 = __ldg(pb + id1), dp2 = __ldg(pb + id2);

        float Px[3], Py[3], Pz[3], Qx[3], Qy[3], Qz[3];
        {
            int ids[3] = {id0, id1, id2};
            float dts[3] = {dt0, dt1, dt2};
            float dps[3] = {dp0, dp1, dp2};
            #pragma unroll
            for (int j = 0; j < 3; j++) {
                int id  = ids[j];
                float u = (float)(id & (WW - 1)) - u0;
                float v = (float)(id >> 10)      - v0;
                float dt = dts[j], dp = dps[j];
                Px[j] = u * dt * invf;  Py[j] = v * dt * invf;  Pz[j] = dt;
                Qx[j] = u * dp * invf;  Qy[j] = v * dp * invf;  Qz[j] = dp;
            }
        }

        // GT diffs: D0 = p2-p1, D1 = p3-p1, D2 = p3-p2
        float Dx[3], Dy[3], Dz[3];
        Dx[0] = Px[1] - Px[0]; Dy[0] = Py[1] - Py[0]; Dz[0] = Pz[1] - Pz[0];
        Dx[1] = Px[2] - Px[0]; Dy[1] = Py[2] - Py[0]; Dz[1] = Pz[2] - Pz[0];
        Dx[2] = Px[2] - Px[1]; Dy[2] = Py[2] - Py[1]; Dz[2] = Pz[2] - Pz[1];

        // Gram matrix of diffs (symmetric)
        float e00 = Dx[0]*Dx[0] + Dy[0]*Dy[0] + Dz[0]*Dz[0];
        float e11 = Dx[1]*Dx[1] + Dy[1]*Dy[1] + Dz[1]*Dz[1];
        float e22 = Dx[2]*Dx[2] + Dy[2]*Dy[2] + Dz[2]*Dz[2];
        float e01 = Dx[0]*Dx[1] + Dy[0]*Dy[1] + Dz[0]*Dz[1];
        float e02 = Dx[0]*Dx[2] + Dy[0]*Dy[2] + Dz[0]*Dz[2];
        float e12 = Dx[1]*Dx[2] + Dy[1]*Dy[2] + Dz[1]*Dz[2];

        float qn0 = sqrtf(e00), qn1 = sqrtf(e11), qn2 = sqrtf(e22);

        // |e/(qn_i*qn_j + EPS)| > DCOS  <=>  |e| > DCOS*(qn_i*qn_j + EPS)
        int cnt = 0;
        cnt += (fabsf(e00) > DCOS * (qn0 * qn0 + EPS)) ? 1 : 0;
        cnt += (fabsf(e11) > DCOS * (qn1 * qn1 + EPS)) ? 1 : 0;
        cnt += (fabsf(e22) > DCOS * (qn2 * qn2 + EPS)) ? 1 : 0;
        cnt += (fabsf(e01) > DCOS * (qn0 * qn1 + EPS)) ? 2 : 0;
        cnt += (fabsf(e02) > DCOS * (qn0 * qn2 + EPS)) ? 2 : 0;
        cnt += (fabsf(e12) > DCOS * (qn1 * qn2 + EPS)) ? 2 : 0;
        bool mask_cos = cnt > 3;

        bool mask_pad = (Pz[0] > DZ) && (Pz[1] > DZ) && (Pz[2] > DZ);
        bool mx = (fabsf(Dx[0]) < DDIFF) || (fabsf(Dx[1]) < DDIFF) || (fabsf(Dx[2]) < DDIFF);
        bool my = (fabsf(Dy[0]) < DDIFF) || (fabsf(Dy[1]) < DDIFF) || (fabsf(Dy[2]) < DDIFF);
        bool mz = (fabsf(Dz[0]) < DDIFF) || (fabsf(Dz[1]) < DDIFF) || (fabsf(Dz[2]) < DDIFF);
        bool valid = mask_pad && !((mx && my && mz) || mask_cos);

        // faithful replication of pred_g[pred_g[:,:,2,:]==0] = 1e-4 broadcast quirk:
        // z of point j == 0  =>  coord j of ALL points := 1e-4
        bool c0 = (Qz[0] == 0.0f), c1 = (Qz[1] == 0.0f), c2 = (Qz[2] == 0.0f);
        if (c0) { Qx[0] = 1e-4f; Qx[1] = 1e-4f; Qx[2] = 1e-4f; }
        if (c1) { Qy[0] = 1e-4f; Qy[1] = 1e-4f; Qy[2] = 1e-4f; }
        if (c2) { Qz[0] = 1e-4f; Qz[1] = 1e-4f; Qz[2] = 1e-4f; }

        // GT normal: cross(D0, D1)
        float ngx = Dy[0] * Dz[1] - Dz[0] * Dy[1];
        float ngy = Dz[0] * Dx[1] - Dx[0] * Dz[1];
        float ngz = Dx[0] * Dy[1] - Dy[0] * Dx[1];
        float nng = sqrtf(ngx * ngx + ngy * ngy + ngz * ngz);
        if (nng == 0.0f) nng = EPS;
        float ig = 1.0f / nng;
        ngx *= ig; ngy *= ig; ngz *= ig;

        // pred normal
        float ax = Qx[1] - Qx[0], ay = Qy[1] - Qy[0], az = Qz[1] - Qz[0];
        float bx = Qx[2] - Qx[0], by = Qy[2] - Qy[0], bz = Qz[2] - Qz[0];
        float npx = ay * bz - az * by;
        float npy = az * bx - ax * bz;
        float npz = ax * by - ay * bx;
        float nnp = sqrtf(npx * npx + npy * npy + npz * npz);
        if (nnp == 0.0f) nnp = EPS;
        float ip = 1.0f / nnp;
        npx *= ip; npy *= ip; npz *= ip;

        float loss = fabsf(ngx - npx) + fabsf(ngy - npy) + fabsf(ngz - npz);

        float out = valid ? loss : INF_F;   // +inf sinks past all finite values
        g_loss[i] = out;
        atomicAdd(&sh[__float_as_uint(out) >> 24], 1u);   // shared, privatized
    }

    __syncthreads();
    unsigned int h = sh[threadIdx.x];
    if (h) atomicAdd(&g_hist8[threadIdx.x], h);
}

// ---------------- resolve top-8: find b8 holding the k-th smallest ----------------
__global__ void resolve8_kernel()
{
    __shared__ unsigned int s[256];
    int t = threadIdx.x;
    s[t] = g_hist8[t];
    __syncthreads();

    if (t == 0) {
        unsigned int n = NTOT - s[0x7f];   // +inf has top8 = 0x7f; finite = valid
        unsigned int k = n >> 2;           // drop n//4 smallest
        g_n = n;

        unsigned int cum = 0; int b8 = 255;
        for (int j = 0; j < 256; j++) {
            unsigned int cj = s[j];
            if (cum + cj >= k) { b8 = j; break; }
            cum += cj;
        }
        g_b8 = (unsigned int)b8;
        g_k1 = k - cum;                    // still needed within bin b8
    }
}

// ---------------- refine: byte-2 hist of values whose top8 == b8 ----------------
__global__ void __launch_bounds__(256)
refine_kernel()
{
    __shared__ unsigned int sh[256];
    sh[threadIdx.x] = 0u;
    __syncthreads();

    unsigned int b8 = g_b8;

    int q = blockIdx.x * blockDim.x + threadIdx.x;
    if (q < NQUAD) {
        float4 v4 = reinterpret_cast<const float4*>(g_loss)[q];
        unsigned int bs[4] = {__float_as_uint(v4.x), __float_as_uint(v4.y),
                              __float_as_uint(v4.z), __float_as_uint(v4.w)};
        #pragma unroll
        for (int e = 0; e < 4; e++) {
            unsigned int bits = bs[e];
            if ((bits >> 24) == b8)
                atomicAdd(&sh[(bits >> 16) & 0xffu], 1u);
        }
    }
    __syncthreads();
    unsigned int h = sh[threadIdx.x];
    if (h) atomicAdd(&g_hist8b[threadIdx.x], h);
}

// ---------------- resolve byte-2: full 16-bit bin + remaining k ----------------
__global__ void resolve16b_kernel()
{
    __shared__ unsigned int s[256];
    int t = threadIdx.x;
    s[t] = g_hist8b[t];
    __syncthreads();

    if (t == 0) {
        unsigned int k1 = g_k1;
        unsigned int cum = 0; int b16 = 255;
        for (int j = 0; j < 256; j++) {
            unsigned int cj = s[j];
            if (cum + cj >= k1) { b16 = j; break; }
            cum += cj;
        }
        g_bin  = (g_b8 << 8) | (unsigned int)b16;
        g_krem = k1 - cum;                 // still needed within the 16-bit bin
    }
}

// ---------------- passB: Σ_valid, Σ(top16<bin), low-16 hist of bin values ----------------
__global__ void __launch_bounds__(256)
passB_kernel()
{
    __shared__ float sh_v[8], sh_b[8];

    unsigned int bsel = g_bin;
    float sv = 0.0f, sb = 0.0f;

    int q = blockIdx.x * blockDim.x + threadIdx.x;
    if (q < NQUAD) {
        float4 v4 = reinterpret_cast<const float4*>(g_loss)[q];
        float vs[4] = {v4.x, v4.y, v4.z, v4.w};
        #pragma unroll
        for (int e = 0; e < 4; e++) {
            float v = vs[e];
            unsigned int bits = __float_as_uint(v);
            if (bits < 0x7f800000u) sv += v;       // finite = valid
            unsigned int top = bits >> 16;
            if (top < bsel) {
                sb += v;
            } else if (top == bsel) {
                atomicAdd(&g_hcnt_lo[bits & 0xffffu], 1u);
                atomicAdd(&g_hsum_lo[bits & 0xffffu], v);
            }
        }
    }

    #pragma unroll
    for (int o = 16; o > 0; o >>= 1) {
        sv += __shfl_down_sync(0xffffffffu, sv, o);
        sb += __shfl_down_sync(0xffffffffu, sb, o);
    }
    int wid = threadIdx.x >> 5, lid = threadIdx.x & 31;
    if (lid == 0) { sh_v[wid] = sv; sh_b[wid] = sb; }
    __syncthreads();
    if (threadIdx.x == 0) {
        float tv = 0.0f, tb = 0.0f;
        #pragma unroll
        for (int w = 0; w < 8; w++) { tv += sh_v[w]; tb += sh_b[w]; }
        atomicAdd(&g_sum_valid, (double)tv);
        atomicAdd(&g_sum_below, (double)tb);
    }
}

// ---------------- resolve low-16 (cooperative) + assemble final scalar ----------------
__global__ void finish_kernel(float* __restrict__ out)
{
    __shared__ unsigned int s_ccnt[256];
    __shared__ float        s_csum[256];
    __shared__ int          s_chunk;
    __shared__ unsigned int s_cum;
    __shared__ double       s_sumfull;
    __shared__ unsigned int s_fcnt[256];
    __shared__ float        s_fsum[256];

    int t = threadIdx.x;

    // per-thread chunk reduction of count AND sum with vector loads
    const uint4*   c4 = reinterpret_cast<const uint4*>(g_hcnt_lo);
    const float4*  f4 = reinterpret_cast<const float4*>(g_hsum_lo);
    unsigned int c = 0;
    float        s = 0.0f;
    int base4 = t << 6;
    #pragma unroll 8
    for (int j = 0; j < 64; j++) {
        uint4  cv = c4[base4 + j];
        float4 sv = f4[base4 + j];
        c += cv.x + cv.y + cv.z + cv.w;
        s += sv.x + sv.y + sv.z + sv.w;
    }
    s_ccnt[t] = c;
    s_csum[t] = s;
    __syncthreads();

    if (t == 0) {
        unsigned int krem = g_krem;
        unsigned int cum = 0; int chunk = 255;
        double sumfull = 0.0;
        for (int ch = 0; ch < 256; ch++) {
            unsigned int cc = s_ccnt[ch];
            if (cum + cc >= krem) { chunk = ch; break; }
            cum += cc;
            sumfull += (double)s_csum[ch];
        }
        s_chunk   = chunk;
        s_cum     = cum;
        s_sumfull = sumfull;
    }
    __syncthreads();

    // cooperatively load the selected chunk's fine bins
    int chunk = s_chunk;
    s_fcnt[t] = g_hcnt_lo[(chunk << 8) + t];
    s_fsum[t] = g_hsum_lo[(chunk << 8) + t];
    __syncthreads();

    if (t == 0) {
        unsigned int krem = g_krem;
        unsigned int cum2 = s_cum;
        double sum_lo_below = s_sumfull;
        unsigned int lobin = (unsigned int)(chunk << 8);
        for (int j = 0; j < 256; j++) {
            unsigned int cj = s_fcnt[j];
            if (cum2 + cj >= krem) { lobin = (unsigned int)((chunk << 8) + j); break; }
            cum2 += cj;
            sum_lo_below += (double)s_fsum[j];
        }
        float tf = __uint_as_float((g_bin << 16) | (lobin & 0xffffu));
        double sum_small = g_sum_below + sum_lo_below
                         + (double)(krem - cum2) * (double)tf;
        unsigned int n = g_n;
        long long d = (long long)n - (long long)(n >> 2);
        if (d < 1) d = 1;
        out[0] = (float)((g_sum_valid - sum_small) / (double)d);
    }
}

// ---------------- launch ----------------
extern "C" void kernel_launch(void* const* d_in, const int* in_sizes, int n_in,
                              void* d_out, int out_size)
{
    const float* pred = (const float*)d_in[0];
    const float* tgt  = (const float*)d_in[1];
    // d_in[2] = mask (already baked into p1/p2/p3; unused)
    const float* intr = (const float*)d_in[3];
    const int*   p1   = (const int*)d_in[4];
    const int*   p2   = (const int*)d_in[5];
    const int*   p3   = (const int*)d_in[6];
    float* out = (float*)d_out;

    init_kernel<<<516, 256>>>();             // 2*65536 + 512 + scalars
    compute_kernel<<<592, 256>>>(pred, tgt, intr, p1, p2, p3);
    resolve8_kernel<<<1, 256>>>();
    refine_kernel<<<(NQUAD + 255) / 256, 256>>>();
    resolve16b_kernel<<<1, 256>>>();
    passB_kernel<<<(NQUAD + 255) / 256, 256>>>();
    finish_kernel<<<1, 256>>>(out);
}

// round 6
// speedup vs baseline: 25.8497x; 1.6315x over previous
#include <cuda_runtime.h>
#include <math.h>

#define BN   8
#define HH   512
#define WW   1024
#define GG   104857
#define NTOT (BN * GG)          // 838856  (divisible by 4)
#define NQUAD (NTOT / 4)        // 209714

// ---------------- device scratch (no allocations allowed) ----------------
__device__ __align__(16) float        g_loss[NTOT];
__device__ __align__(16) unsigned int g_hist8[256];   // top-8-bit counts
__device__ __align__(16) unsigned int g_cnt2[256];    // byte-2 counts (top8==b8)
__device__ __align__(16) float        g_fsum2[256];   // byte-2 sums   (top8==b8)
__device__ double       g_sum_valid;
__device__ double       g_sum_below;                  // Σ values with top8 < b8
__device__ unsigned int g_n;
__device__ unsigned int g_b8;
__device__ unsigned int g_k1;

// ---------------- init: clear small histograms + scalars ----------------
__global__ void init_kernel() {
    int t = threadIdx.x;
    g_hist8[t] = 0u;
    g_cnt2[t]  = 0u;
    g_fsum2[t] = 0.0f;
    if (t == 0) { g_sum_valid = 0.0; g_sum_below = 0.0; }
}

// ---------------- main compute: loss + Σ_valid + top-8 shared hist ----------------
__global__ void __launch_bounds__(256)
compute_kernel(const float* __restrict__ pred,
               const float* __restrict__ tgt,
               const float* __restrict__ intr,
               const int*   __restrict__ p1,
               const int*   __restrict__ p2,
               const int*   __restrict__ p3)
{
    __shared__ unsigned int sh[256];
    __shared__ float        sh_sum[8];
    sh[threadIdx.x] = 0u;
    __syncthreads();

    const float EPS   = 1e-6f;
    const float DCOS  = 0.867f;
    const float DDIFF = 0.005f;
    const float DZ    = 1e-5f;
    const float INF_F = __int_as_float(0x7f800000);

    float local_sum = 0.0f;

    for (int i = blockIdx.x * blockDim.x + threadIdx.x; i < NTOT;
         i += gridDim.x * blockDim.x)
    {
        int b = i / GG;
        const float* tb = tgt  + b * (HH * WW);
        const float* pb = pred + b * (HH * WW);
        float f    = __ldg(intr + b * 9 + 0);
        float u0   = __ldg(intr + b * 9 + 2);
        float v0   = __ldg(intr + b * 9 + 5);
        float invf = 1.0f / f;

        int id0 = __ldg(p1 + i);
        int id1 = __ldg(p2 + i);
        int id2 = __ldg(p3 + i);

        // issue all gathers up front for MLP
        float dt0 = __ldg(tb + id0), dt1 = __ldg(tb + id1), dt2 = __ldg(tb + id2);
        float dp0 = __ldg(pb + id0), dp1 = __ldg(pb + id1), dp2 = __ldg(pb + id2);

        float Px[3], Py[3], Pz[3], Qx[3], Qy[3], Qz[3];
        {
            int ids[3] = {id0, id1, id2};
            float dts[3] = {dt0, dt1, dt2};
            float dps[3] = {dp0, dp1, dp2};
            #pragma unroll
            for (int j = 0; j < 3; j++) {
                int id  = ids[j];
                float u = (float)(id & (WW - 1)) - u0;
                float v = (float)(id >> 10)      - v0;
                float dt = dts[j], dp = dps[j];
                Px[j] = u * dt * invf;  Py[j] = v * dt * invf;  Pz[j] = dt;
                Qx[j] = u * dp * invf;  Qy[j] = v * dp * invf;  Qz[j] = dp;
            }
        }

        // GT diffs: D0 = p2-p1, D1 = p3-p1, D2 = p3-p2
        float Dx[3], Dy[3], Dz[3];
        Dx[0] = Px[1] - Px[0]; Dy[0] = Py[1] - Py[0]; Dz[0] = Pz[1] - Pz[0];
        Dx[1] = Px[2] - Px[0]; Dy[1] = Py[2] - Py[0]; Dz[1] = Pz[2] - Pz[0];
        Dx[2] = Px[2] - Px[1]; Dy[2] = Py[2] - Py[1]; Dz[2] = Pz[2] - Pz[1];

        // Gram matrix of diffs (symmetric)
        float e00 = Dx[0]*Dx[0] + Dy[0]*Dy[0] + Dz[0]*Dz[0];
        float e11 = Dx[1]*Dx[1] + Dy[1]*Dy[1] + Dz[1]*Dz[1];
        float e22 = Dx[2]*Dx[2] + Dy[2]*Dy[2] + Dz[2]*Dz[2];
        float e01 = Dx[0]*Dx[1] + Dy[0]*Dy[1] + Dz[0]*Dz[1];
        float e02 = Dx[0]*Dx[2] + Dy[0]*Dy[2] + Dz[0]*Dz[2];
        float e12 = Dx[1]*Dx[2] + Dy[1]*Dy[2] + Dz[1]*Dz[2];

        // diagonals: qn_i*qn_i == e_ii (no sqrt needed)
        // off-diag:  qn_i*qn_j == sqrt(e_ii*e_jj)
        float p01 = sqrtf(e00 * e11);
        float p02 = sqrtf(e00 * e22);
        float p12 = sqrtf(e11 * e22);

        int cnt = 0;
        cnt += (e00 > DCOS * (e00 + EPS)) ? 1 : 0;
        cnt += (e11 > DCOS * (e11 + EPS)) ? 1 : 0;
        cnt += (e22 > DCOS * (e22 + EPS)) ? 1 : 0;
        cnt += (fabsf(e01) > DCOS * (p01 + EPS)) ? 2 : 0;
        cnt += (fabsf(e02) > DCOS * (p02 + EPS)) ? 2 : 0;
        cnt += (fabsf(e12) > DCOS * (p12 + EPS)) ? 2 : 0;
        bool mask_cos = cnt > 3;

        bool mask_pad = (Pz[0] > DZ) && (Pz[1] > DZ) && (Pz[2] > DZ);
        bool mx = (fabsf(Dx[0]) < DDIFF) || (fabsf(Dx[1]) < DDIFF) || (fabsf(Dx[2]) < DDIFF);
        bool my = (fabsf(Dy[0]) < DDIFF) || (fabsf(Dy[1]) < DDIFF) || (fabsf(Dy[2]) < DDIFF);
        bool mz = (fabsf(Dz[0]) < DDIFF) || (fabsf(Dz[1]) < DDIFF) || (fabsf(Dz[2]) < DDIFF);
        bool valid = mask_pad && !((mx && my && mz) || mask_cos);

        // faithful replication of pred_g[pred_g[:,:,2,:]==0] = 1e-4 broadcast quirk:
        // z of point j == 0  =>  coord j of ALL points := 1e-4
        bool c0 = (Qz[0] == 0.0f), c1 = (Qz[1] == 0.0f), c2 = (Qz[2] == 0.0f);
        if (c0) { Qx[0] = 1e-4f; Qx[1] = 1e-4f; Qx[2] = 1e-4f; }
        if (c1) { Qy[0] = 1e-4f; Qy[1] = 1e-4f; Qy[2] = 1e-4f; }
        if (c2) { Qz[0] = 1e-4f; Qz[1] = 1e-4f; Qz[2] = 1e-4f; }

        // GT normal: cross(D0, D1)
        float ngx = Dy[0] * Dz[1] - Dz[0] * Dy[1];
        float ngy = Dz[0] * Dx[1] - Dx[0] * Dz[1];
        float ngz = Dx[0] * Dy[1] - Dy[0] * Dx[1];
        float nng = sqrtf(ngx * ngx + ngy * ngy + ngz * ngz);
        if (nng == 0.0f) nng = EPS;
        float ig = 1.0f / nng;
        ngx *= ig; ngy *= ig; ngz *= ig;

        // pred normal
        float ax = Qx[1] - Qx[0], ay = Qy[1] - Qy[0], az = Qz[1] - Qz[0];
        float bx = Qx[2] - Qx[0], by = Qy[2] - Qy[0], bz = Qz[2] - Qz[0];
        float npx = ay * bz - az * by;
        float npy = az * bx - ax * bz;
        float npz = ax * by - ay * bx;
        float nnp = sqrtf(npx * npx + npy * npy + npz * npz);
        if (nnp == 0.0f) nnp = EPS;
        float ip = 1.0f / nnp;
        npx *= ip; npy *= ip; npz *= ip;

        float loss = fabsf(ngx - npx) + fabsf(ngy - npy) + fabsf(ngz - npz);

        float out = valid ? loss : INF_F;   // +inf sinks past all finite values
        g_loss[i] = out;
        if (valid) local_sum += loss;
        atomicAdd(&sh[__float_as_uint(out) >> 24], 1u);   // shared, privatized
    }

    // block reduction of valid-sum
    float s = local_sum;
    #pragma unroll
    for (int o = 16; o > 0; o >>= 1)
        s += __shfl_down_sync(0xffffffffu, s, o);
    int wid = threadIdx.x >> 5, lid = threadIdx.x & 31;
    if (lid == 0) sh_sum[wid] = s;
    __syncthreads();
    if (threadIdx.x == 0) {
        float ts = 0.0f;
        #pragma unroll
        for (int w = 0; w < 8; w++) ts += sh_sum[w];
        atomicAdd(&g_sum_valid, (double)ts);
    }
    unsigned int h = sh[threadIdx.x];
    if (h) atomicAdd(&g_hist8[threadIdx.x], h);
}

// ---------------- resolve top-8: parallel prefix scan ----------------
__global__ void resolve8_kernel()
{
    __shared__ unsigned int s[256];
    __shared__ unsigned int s_n;

    int t = threadIdx.x;
    unsigned int c = g_hist8[t];
    if (t == 0x7f) s_n = NTOT - c;      // +inf has top8 = 0x7f; finite = valid
    s[t] = c;
    __syncthreads();

    // Hillis-Steele inclusive scan
    #pragma unroll
    for (int o = 1; o < 256; o <<= 1) {
        unsigned int v = (t >= o) ? s[t - o] : 0u;
        __syncthreads();
        s[t] += v;
        __syncthreads();
    }

    unsigned int n = s_n;
    unsigned int k = n >> 2;            // drop n//4 smallest
    unsigned int below = (t > 0) ? s[t - 1] : 0u;
    if (s[t] >= k && below < k) {       // exactly one thread fires
        g_b8 = (unsigned int)t;
        g_k1 = k - below;
        g_n  = n;
    }
}

// ---------------- passC: Σ(top8<b8) + byte-2 cnt/sum hist for top8==b8 ----------------
__global__ void __launch_bounds__(256)
passC_kernel()
{
    __shared__ unsigned int sh_c[256];
    __shared__ float        sh_f[256];
    __shared__ float        sh_b[8];

    sh_c[threadIdx.x] = 0u;
    sh_f[threadIdx.x] = 0.0f;
    __syncthreads();

    unsigned int b8 = g_b8;
    float sb = 0.0f;

    int q = blockIdx.x * blockDim.x + threadIdx.x;
    if (q < NQUAD) {
        float4 v4 = reinterpret_cast<const float4*>(g_loss)[q];
        float vs[4] = {v4.x, v4.y, v4.z, v4.w};
        #pragma unroll
        for (int e = 0; e < 4; e++) {
            float v = vs[e];
            unsigned int bits = __float_as_uint(v);
            unsigned int top = bits >> 24;
            if (top < b8) {
                sb += v;
            } else if (top == b8) {
                unsigned int j = (bits >> 16) & 0xffu;
                atomicAdd(&sh_c[j], 1u);
                atomicAdd(&sh_f[j], v);
            }
        }
    }

    #pragma unroll
    for (int o = 16; o > 0; o >>= 1)
        sb += __shfl_down_sync(0xffffffffu, sb, o);
    int wid = threadIdx.x >> 5, lid = threadIdx.x & 31;
    if (lid == 0) sh_b[wid] = sb;
    __syncthreads();
    if (threadIdx.x == 0) {
        float tb = 0.0f;
        #pragma unroll
        for (int w = 0; w < 8; w++) tb += sh_b[w];
        atomicAdd(&g_sum_below, (double)tb);
    }
    unsigned int hc = sh_c[threadIdx.x];
    if (hc) {
        atomicAdd(&g_cnt2[threadIdx.x], hc);
        atomicAdd(&g_fsum2[threadIdx.x], sh_f[threadIdx.x]);
    }
}

// ---------------- finish: pick byte-2 bin, assemble scalar ----------------
__global__ void finish_kernel(float* __restrict__ out)
{
    __shared__ unsigned int s_c[256];
    __shared__ float        s_f[256];

    int t = threadIdx.x;
    s_c[t] = g_cnt2[t];
    s_f[t] = g_fsum2[t];
    __syncthreads();

    if (t == 0) {
        unsigned int k1 = g_k1;
        unsigned int b8 = g_b8;

        unsigned int cum = 0; int j = 255;
        double sum_full = 0.0;
        for (int jj = 0; jj < 256; jj++) {
            unsigned int cj = s_c[jj];
            if (cum + cj >= k1) { j = jj; break; }
            cum += cj;
            sum_full += (double)s_f[jj];
        }
        // partial bin priced at its lower edge (error << 1e-3 relative)
        float tf = __uint_as_float((b8 << 24) | ((unsigned int)j << 16));
        double sum_small = g_sum_below + sum_full
                         + (double)(k1 - cum) * (double)tf;
        unsigned int n = g_n;
        long long d = (long long)n - (long long)(n >> 2);
        if (d < 1) d = 1;
        out[0] = (float)((g_sum_valid - sum_small) / (double)d);
    }
}

// ---------------- launch ----------------
extern "C" void kernel_launch(void* const* d_in, const int* in_sizes, int n_in,
                              void* d_out, int out_size)
{
    const float* pred = (const float*)d_in[0];
    const float* tgt  = (const float*)d_in[1];
    // d_in[2] = mask (already baked into p1/p2/p3; unused)
    const float* intr = (const float*)d_in[3];
    const int*   p1   = (const int*)d_in[4];
    const int*   p2   = (const int*)d_in[5];
    const int*   p3   = (const int*)d_in[6];
    float* out = (float*)d_out;

    init_kernel<<<1, 256>>>();
    compute_kernel<<<592, 256>>>(pred, tgt, intr, p1, p2, p3);
    resolve8_kernel<<<1, 256>>>();
    passC_kernel<<<(NQUAD + 255) / 256, 256>>>();
    finish_kernel<<<1, 256>>>(out);
}

// round 7
// speedup vs baseline: 26.1559x; 1.0118x over previous
#include <cuda_runtime.h>
#include <math.h>

#define BN   8
#define HH   512
#define WW   1024
#define GG   104857
#define NTOT (BN * GG)          // 838856  (divisible by 4)
#define NQUAD (NTOT / 4)        // 209714
#define NHALF (NTOT / 2)        // 419428

// ---------------- device scratch (no allocations allowed) ----------------
// All scratch is zero at module load; finish_kernel re-zeroes it at the end
// of every run, so each kernel_launch starts from a clean state.
__device__ __align__(16) float        g_loss[NTOT];
__device__ __align__(16) unsigned int g_hist8[256];   // top-8-bit counts
__device__ __align__(16) unsigned int g_cnt2[256];    // byte-2 counts (top8==b8)
__device__ __align__(16) float        g_fsum2[256];   // byte-2 sums   (top8==b8)
__device__ double       g_sum_valid;
__device__ double       g_sum_below;                  // Σ values with top8 < b8
__device__ unsigned int g_n;
__device__ unsigned int g_b8;
__device__ unsigned int g_k1;

// ---------------- main compute: loss + Σ_valid + top-8 shared hist ----------------
// 2 elements per thread (i, i+NHALF) -> 12 independent gathers in flight.
__global__ void __launch_bounds__(256)
compute_kernel(const float* __restrict__ pred,
               const float* __restrict__ tgt,
               const float* __restrict__ intr,
               const int*   __restrict__ p1,
               const int*   __restrict__ p2,
               const int*   __restrict__ p3)
{
    __shared__ unsigned int sh[256];
    __shared__ float        sh_sum[8];
    sh[threadIdx.x] = 0u;
    __syncthreads();

    const float EPS   = 1e-6f;
    const float DCOS  = 0.867f;
    const float DDIFF = 0.005f;
    const float DZ    = 1e-5f;
    const float INF_F = __int_as_float(0x7f800000);

    float local_sum = 0.0f;

    int t = blockIdx.x * blockDim.x + threadIdx.x;

    // ---- batched front loads for both elements (max MLP) ----
    int   idx[2][3];
    float dtv[2][3], dpv[2][3];
    bool  act[2];
    int   ii[2] = { t, t + NHALF };

    #pragma unroll
    for (int r = 0; r < 2; r++) {
        act[r] = (ii[r] < NTOT);
        int i = act[r] ? ii[r] : 0;
        idx[r][0] = __ldg(p1 + i);
        idx[r][1] = __ldg(p2 + i);
        idx[r][2] = __ldg(p3 + i);
    }
    #pragma unroll
    for (int r = 0; r < 2; r++) {
        int i = act[r] ? ii[r] : 0;
        int b = i / GG;
        const float* tb = tgt  + b * (HH * WW);
        const float* pb = pred + b * (HH * WW);
        #pragma unroll
        for (int j = 0; j < 3; j++) {
            dtv[r][j] = __ldg(tb + idx[r][j]);
            dpv[r][j] = __ldg(pb + idx[r][j]);
        }
    }

    #pragma unroll
    for (int r = 0; r < 2; r++) {
        if (!act[r]) continue;
        int i = ii[r];
        int b = i / GG;
        float f    = __ldg(intr + b * 9 + 0);
        float u0   = __ldg(intr + b * 9 + 2);
        float v0   = __ldg(intr + b * 9 + 5);
        float invf = 1.0f / f;

        float Px[3], Py[3], Pz[3], Qx[3], Qy[3], Qz[3];
        #pragma unroll
        for (int j = 0; j < 3; j++) {
            int id  = idx[r][j];
            float u = (float)(id & (WW - 1)) - u0;
            float v = (float)(id >> 10)      - v0;
            float dt = dtv[r][j], dp = dpv[r][j];
            Px[j] = u * dt * invf;  Py[j] = v * dt * invf;  Pz[j] = dt;
            Qx[j] = u * dp * invf;  Qy[j] = v * dp * invf;  Qz[j] = dp;
        }

        // GT diffs: D0 = p2-p1, D1 = p3-p1, D2 = p3-p2
        float Dx[3], Dy[3], Dz[3];
        Dx[0] = Px[1] - Px[0]; Dy[0] = Py[1] - Py[0]; Dz[0] = Pz[1] - Pz[0];
        Dx[1] = Px[2] - Px[0]; Dy[1] = Py[2] - Py[0]; Dz[1] = Pz[2] - Pz[0];
        Dx[2] = Px[2] - Px[1]; Dy[2] = Py[2] - Py[1]; Dz[2] = Pz[2] - Pz[1];

        // Gram matrix of diffs (symmetric)
        float e00 = Dx[0]*Dx[0] + Dy[0]*Dy[0] + Dz[0]*Dz[0];
        float e11 = Dx[1]*Dx[1] + Dy[1]*Dy[1] + Dz[1]*Dz[1];
        float e22 = Dx[2]*Dx[2] + Dy[2]*Dy[2] + Dz[2]*Dz[2];
        float e01 = Dx[0]*Dx[1] + Dy[0]*Dy[1] + Dz[0]*Dz[1];
        float e02 = Dx[0]*Dx[2] + Dy[0]*Dy[2] + Dz[0]*Dz[2];
        float e12 = Dx[1]*Dx[2] + Dy[1]*Dy[2] + Dz[1]*Dz[2];

        // diag: qn_i*qn_i == e_ii ; off-diag: qn_i*qn_j == sqrt(e_ii*e_jj)
        float p01 = sqrtf(e00 * e11);
        float p02 = sqrtf(e00 * e22);
        float p12 = sqrtf(e11 * e22);

        int cnt = 0;
        cnt += (e00 > DCOS * (e00 + EPS)) ? 1 : 0;
        cnt += (e11 > DCOS * (e11 + EPS)) ? 1 : 0;
        cnt += (e22 > DCOS * (e22 + EPS)) ? 1 : 0;
        cnt += (fabsf(e01) > DCOS * (p01 + EPS)) ? 2 : 0;
        cnt += (fabsf(e02) > DCOS * (p02 + EPS)) ? 2 : 0;
        cnt += (fabsf(e12) > DCOS * (p12 + EPS)) ? 2 : 0;
        bool mask_cos = cnt > 3;

        bool mask_pad = (Pz[0] > DZ) && (Pz[1] > DZ) && (Pz[2] > DZ);
        bool mx = (fabsf(Dx[0]) < DDIFF) || (fabsf(Dx[1]) < DDIFF) || (fabsf(Dx[2]) < DDIFF);
        bool my = (fabsf(Dy[0]) < DDIFF) || (fabsf(Dy[1]) < DDIFF) || (fabsf(Dy[2]) < DDIFF);
        bool mz = (fabsf(Dz[0]) < DDIFF) || (fabsf(Dz[1]) < DDIFF) || (fabsf(Dz[2]) < DDIFF);
        bool valid = mask_pad && !((mx && my && mz) || mask_cos);

        // faithful replication of pred_g[pred_g[:,:,2,:]==0] = 1e-4 broadcast quirk:
        // z of point j == 0  =>  coord j of ALL points := 1e-4
        bool c0 = (Qz[0] == 0.0f), c1 = (Qz[1] == 0.0f), c2 = (Qz[2] == 0.0f);
        if (c0) { Qx[0] = 1e-4f; Qx[1] = 1e-4f; Qx[2] = 1e-4f; }
        if (c1) { Qy[0] = 1e-4f; Qy[1] = 1e-4f; Qy[2] = 1e-4f; }
        if (c2) { Qz[0] = 1e-4f; Qz[1] = 1e-4f; Qz[2] = 1e-4f; }

        // GT normal: cross(D0, D1)
        float ngx = Dy[0] * Dz[1] - Dz[0] * Dy[1];
        float ngy = Dz[0] * Dx[1] - Dx[0] * Dz[1];
        float ngz = Dx[0] * Dy[1] - Dy[0] * Dx[1];
        float nng = sqrtf(ngx * ngx + ngy * ngy + ngz * ngz);
        if (nng == 0.0f) nng = EPS;
        float ig = 1.0f / nng;
        ngx *= ig; ngy *= ig; ngz *= ig;

        // pred normal
        float ax = Qx[1] - Qx[0], ay = Qy[1] - Qy[0], az = Qz[1] - Qz[0];
        float bx = Qx[2] - Qx[0], by = Qy[2] - Qy[0], bz = Qz[2] - Qz[0];
        float npx = ay * bz - az * by;
        float npy = az * bx - ax * bz;
        float npz = ax * by - ay * bx;
        float nnp = sqrtf(npx * npx + npy * npy + npz * npz);
        if (nnp == 0.0f) nnp = EPS;
        float ip = 1.0f / nnp;
        npx *= ip; npy *= ip; npz *= ip;

        float loss = fabsf(ngx - npx) + fabsf(ngy - npy) + fabsf(ngz - npz);

        float out = valid ? loss : INF_F;   // +inf sinks past all finite values
        g_loss[i] = out;
        if (valid) local_sum += loss;
        atomicAdd(&sh[__float_as_uint(out) >> 24], 1u);   // shared, privatized
    }

    // block reduction of valid-sum
    float s = local_sum;
    #pragma unroll
    for (int o = 16; o > 0; o >>= 1)
        s += __shfl_down_sync(0xffffffffu, s, o);
    int wid = threadIdx.x >> 5, lid = threadIdx.x & 31;
    if (lid == 0) sh_sum[wid] = s;
    __syncthreads();
    if (threadIdx.x == 0) {
        float ts = 0.0f;
        #pragma unroll
        for (int w = 0; w < 8; w++) ts += sh_sum[w];
        atomicAdd(&g_sum_valid, (double)ts);
    }
    unsigned int h = sh[threadIdx.x];
    if (h) atomicAdd(&g_hist8[threadIdx.x], h);
}

// ---------------- resolve top-8: parallel prefix scan ----------------
__global__ void resolve8_kernel()
{
    __shared__ unsigned int s[256];
    __shared__ unsigned int s_n;

    int t = threadIdx.x;
    unsigned int c = g_hist8[t];
    if (t == 0x7f) s_n = NTOT - c;      // +inf has top8 = 0x7f; finite = valid
    s[t] = c;
    __syncthreads();

    // Hillis-Steele inclusive scan
    #pragma unroll
    for (int o = 1; o < 256; o <<= 1) {
        unsigned int v = (t >= o) ? s[t - o] : 0u;
        __syncthreads();
        s[t] += v;
        __syncthreads();
    }

    unsigned int n = s_n;
    unsigned int k = n >> 2;            // drop n//4 smallest
    unsigned int below = (t > 0) ? s[t - 1] : 0u;
    if (s[t] >= k && below < k) {       // exactly one thread fires
        g_b8 = (unsigned int)t;
        g_k1 = k - below;
        g_n  = n;
    }
}

// ---------------- passC: Σ(top8<b8) + byte-2 cnt/sum hist for top8==b8 ----------------
// 4 float4 per thread, loads batched up front.
#define PC_BLOCKS 205
#define PC_STRIDE (PC_BLOCKS * 256)     // 52480
__global__ void __launch_bounds__(256)
passC_kernel()
{
    __shared__ unsigned int sh_c[256];
    __shared__ float        sh_f[256];
    __shared__ float        sh_b[8];

    sh_c[threadIdx.x] = 0u;
    sh_f[threadIdx.x] = 0.0f;
    __syncthreads();

    unsigned int b8 = g_b8;
    float sb = 0.0f;

    int t = blockIdx.x * blockDim.x + threadIdx.x;
    const float4* L4 = reinterpret_cast<const float4*>(g_loss);

    float4 v[4];
    bool   ok[4];
    #pragma unroll
    for (int j = 0; j < 4; j++) {
        int q = t + j * PC_STRIDE;
        ok[j] = (q < NQUAD);
        v[j]  = L4[ok[j] ? q : 0];
    }

    #pragma unroll
    for (int j = 0; j < 4; j++) {
        if (!ok[j]) continue;
        float vs[4] = {v[j].x, v[j].y, v[j].z, v[j].w};
        #pragma unroll
        for (int e = 0; e < 4; e++) {
            float val = vs[e];
            unsigned int bits = __float_as_uint(val);
            unsigned int top = bits >> 24;
            if (top < b8) {
                sb += val;
            } else if (top == b8) {
                unsigned int bj = (bits >> 16) & 0xffu;
                atomicAdd(&sh_c[bj], 1u);
                atomicAdd(&sh_f[bj], val);
            }
        }
    }

    #pragma unroll
    for (int o = 16; o > 0; o >>= 1)
        sb += __shfl_down_sync(0xffffffffu, sb, o);
    int wid = threadIdx.x >> 5, lid = threadIdx.x & 31;
    if (lid == 0) sh_b[wid] = sb;
    __syncthreads();
    if (threadIdx.x == 0) {
        float tb = 0.0f;
        #pragma unroll
        for (int w = 0; w < 8; w++) tb += sh_b[w];
        atomicAdd(&g_sum_below, (double)tb);
    }
    unsigned int hc = sh_c[threadIdx.x];
    if (hc) {
        atomicAdd(&g_cnt2[threadIdx.x], hc);
        atomicAdd(&g_fsum2[threadIdx.x], sh_f[threadIdx.x]);
    }
}

// ---------------- finish: pick byte-2 bin, assemble scalar, reset scratch ----------------
__global__ void finish_kernel(float* __restrict__ out)
{
    __shared__ unsigned int s_c[256];
    __shared__ float        s_f[256];

    int t = threadIdx.x;
    s_c[t] = g_cnt2[t];
    s_f[t] = g_fsum2[t];
    __syncthreads();

    if (t == 0) {
        unsigned int k1 = g_k1;
        unsigned int b8 = g_b8;

        unsigned int cum = 0; int j = 255;
        double sum_full = 0.0;
        for (int jj = 0; jj < 256; jj++) {
            unsigned int cj = s_c[jj];
            if (cum + cj >= k1) { j = jj; break; }
            cum += cj;
            sum_full += (double)s_f[jj];
        }
        // partial bin priced at its lower edge (error << 1e-3 relative)
        float tf = __uint_as_float((b8 << 24) | ((unsigned int)j << 16));
        double sum_small = g_sum_below + sum_full
                         + (double)(k1 - cum) * (double)tf;
        unsigned int n = g_n;
        long long d = (long long)n - (long long)(n >> 2);
        if (d < 1) d = 1;
        out[0] = (float)((g_sum_valid - sum_small) / (double)d);
    }
    __syncthreads();

    // reset scratch so the next run starts from zeros (replaces init_kernel)
    g_hist8[t] = 0u;
    g_cnt2[t]  = 0u;
    g_fsum2[t] = 0.0f;
    if (t == 0) { g_sum_valid = 0.0; g_sum_below = 0.0; }
}

// ---------------- launch ----------------
extern "C" void kernel_launch(void* const* d_in, const int* in_sizes, int n_in,
                              void* d_out, int out_size)
{
    const float* pred = (const float*)d_in[0];
    const float* tgt  = (const float*)d_in[1];
    // d_in[2] = mask (already baked into p1/p2/p3; unused)
    const float* intr = (const float*)d_in[3];
    const int*   p1   = (const int*)d_in[4];
    const int*   p2   = (const int*)d_in[5];
    const int*   p3   = (const int*)d_in[6];
    float* out = (float*)d_out;

    compute_kernel<<<(NHALF + 255) / 256, 256>>>(pred, tgt, intr, p1, p2, p3);
    resolve8_kernel<<<1, 256>>>();
    passC_kernel<<<PC_BLOCKS, 256>>>();
    finish_kernel<<<1, 256>>>(out);
}